// round 9
// baseline (speedup 1.0000x reference)
#include <cuda_runtime.h>

// Final shape tune: 128-thread CTAs (512 rows/CTA, grid 32768).
//  - Same per-instruction coalescing (warp covers contiguous 512B per LDG/STG.128)
//  - Same MLP_p1=4 front-batched loads
//  - Same __ldcs/__stcs streaming eviction
//  - 2x finer CTA granularity -> smaller end-of-kernel straggler tail,
//    shallower per-CTA L1tex queue burst (spread model: spr ~ oe*MLP_p1).
__global__ void __launch_bounds__(128)
quantum_probs_kernel_bs4s128(const float4* __restrict__ in,
                             float4* __restrict__ out,
                             int n) {
    const int tid = threadIdx.x;
    const int stride = blockDim.x;
    const int base = blockIdx.x * (stride * 4) + tid;

    if (base + 3 * stride < n) {
        float4 r0 = __ldcs(&in[base + 0 * stride]);
        float4 r1 = __ldcs(&in[base + 1 * stride]);
        float4 r2 = __ldcs(&in[base + 2 * stride]);
        float4 r3 = __ldcs(&in[base + 3 * stride]);

        float s, c;
        __sincosf(r0.x * 0.5f, &s, &c);
        float c20 = c * c, s20 = s * s;
        __sincosf(r1.x * 0.5f, &s, &c);
        float c21 = c * c, s21 = s * s;
        __sincosf(r2.x * 0.5f, &s, &c);
        float c22 = c * c, s22 = s * s;
        __sincosf(r3.x * 0.5f, &s, &c);
        float c23 = c * c, s23 = s * s;

        __stcs(&out[base + 0 * stride], make_float4(c20 * c20, c20 * s20, s20 * s20, s20 * c20));
        __stcs(&out[base + 1 * stride], make_float4(c21 * c21, c21 * s21, s21 * s21, s21 * c21));
        __stcs(&out[base + 2 * stride], make_float4(c22 * c22, c22 * s22, s22 * s22, s22 * c22));
        __stcs(&out[base + 3 * stride], make_float4(c23 * c23, c23 * s23, s23 * s23, s23 * c23));
    } else {
        // Tail path (not taken for N = 16M: 512 rows/block divides N)
        for (int i = base; i < n; i += stride) {
            float4 rr = __ldcs(&in[i]);
            float s, c;
            __sincosf(rr.x * 0.5f, &s, &c);
            float c2 = c * c, s2 = s * s;
            __stcs(&out[i], make_float4(c2 * c2, c2 * s2, s2 * s2, s2 * c2));
        }
    }
}

extern "C" void kernel_launch(void* const* d_in, const int* in_sizes, int n_in,
                              void* d_out, int out_size) {
    const float4* in = (const float4*)d_in[0];
    float4* out = (float4*)d_out;
    int n = in_sizes[0] / 4;                  // N rows
    int threads = 128;
    int rows_per_block = threads * 4;
    int blocks = (n + rows_per_block - 1) / rows_per_block;
    quantum_probs_kernel_bs4s128<<<blocks, threads>>>(in, out, n);
}